// round 6
// baseline (speedup 1.0000x reference)
#include <cuda_runtime.h>
#include <math_constants.h>

#define B_ 4
#define S_ 512
#define D_ 768
#define MAX_LEN_ 10
#define LEN_EMB_ 25
#define NUM_LABELS_ 9
#define N_ (S_ * MAX_LEN_)   // 5120
#define GRID_ 683            // persistent: each block handles ~3 (b,s) tasks

// len_logits[L-1][c] = len_emb_table[L-1] . W[768:, c] + b[c]
__device__ float g_len_logits[MAX_LEN_ * NUM_LABELS_];
// Transposed W head: Wt[c][d] = W[d][c]
__device__ __align__(16) float g_Wt[NUM_LABELS_][D_];

__global__ void prep_kernel(const float* __restrict__ len_emb_table,
                            const float* __restrict__ W,
                            const float* __restrict__ bvec) {
    int i = blockIdx.x * 256 + threadIdx.x;
    if (i < NUM_LABELS_ * D_) {
        int c = i / D_;
        int d = i % D_;
        g_Wt[c][d] = W[(size_t)d * NUM_LABELS_ + c];
    }
    if (blockIdx.x == 0 && threadIdx.x < MAX_LEN_ * NUM_LABELS_) {
        int L = threadIdx.x / NUM_LABELS_;
        int c = threadIdx.x % NUM_LABELS_;
        float s = bvec[c];
        #pragma unroll
        for (int k = 0; k < LEN_EMB_; k++) {
            s = fmaf(len_emb_table[L * LEN_EMB_ + k], W[(D_ + k) * NUM_LABELS_ + c], s);
        }
        g_len_logits[threadIdx.x] = s;
    }
}

__device__ __forceinline__ float4 max4(float4 a, float4 b) {
    float4 r;
    r.x = fmaxf(a.x, b.x); r.y = fmaxf(a.y, b.y);
    r.z = fmaxf(a.z, b.z); r.w = fmaxf(a.w, b.w);
    return r;
}

// Fused design, warp-autonomous (NO block barriers, NO pooled smem):
// Warp w of each block owns columns [3w, 3w+3) with its W slice in registers
// (amortized over 3 grid-stride tasks). Per task, the warp streams the 10
// (clamped) rows from global, maintains the running prefix-max of its 24 dims
// per lane, and immediately emits the 3 column partials for span j=r into
// warp-private smem scratch. One conflict-free transpose-reduce per task.
__global__ __launch_bounds__(96, 5) void span_ner_kernel(
    const float* __restrict__ we,       // [B, S, D]
    const int*   __restrict__ starts,   // [B, N]
    const int*   __restrict__ lens,     // [B, N]
    float*       __restrict__ out)      // [B, N, 9]
{
    __shared__ float redw_s[3][30][36]; // per-warp scratch, 12.7 KB

    const int lane = threadIdx.x & 31;
    const int wid  = threadIdx.x >> 5;
    const int c0   = wid * 3;
    float* const redw = &redw_s[wid][0][0];

    // W slice in registers: lane owns dims 4*(lane+32k), k in [0,6). 72 regs.
    float4 Wr[6][3];
    #pragma unroll
    for (int k = 0; k < 6; k++) {
        #pragma unroll
        for (int t = 0; t < 3; t++) {
            Wr[k][t] = *(const float4*)&g_Wt[c0 + t][4 * (lane + 32 * k)];
        }
    }

    for (int bs = blockIdx.x; bs < B_ * S_; bs += GRID_) {
        const int b = bs >> 9;
        const int s = bs & (S_ - 1);

        const size_t bn = (size_t)b * N_ + (size_t)s * MAX_LEN_;
        const int start = starts[bn];
        const int smax1 = S_ - start - 1;        // >= 0
        const float* base = we + ((size_t)b * S_ + start) * D_;

        float4 m[6];
        #pragma unroll
        for (int k = 0; k < 6; k++)
            m[k] = make_float4(-CUDART_INF_F, -CUDART_INF_F, -CUDART_INF_F, -CUDART_INF_F);

        // Stream rows; pooled(j) = prefix max through clamped row j
        // (duplicated clamped rows are idempotent under max).
        #pragma unroll 1
        for (int r = 0; r < MAX_LEN_; r++) {
            const int rc = (r < smax1) ? r : smax1;
            const float* rowp = base + (size_t)rc * D_;
            float4 v[6];
            #pragma unroll
            for (int k = 0; k < 6; k++)
                v[k] = __ldg((const float4*)(rowp + 4 * (lane + 32 * k)));
            #pragma unroll
            for (int k = 0; k < 6; k++)
                m[k] = max4(m[k], v[k]);

            float a0 = 0.f, a1 = 0.f, a2 = 0.f;
            #pragma unroll
            for (int k = 0; k < 6; k++) {
                a0 = fmaf(m[k].x, Wr[k][0].x, a0); a1 = fmaf(m[k].x, Wr[k][1].x, a1); a2 = fmaf(m[k].x, Wr[k][2].x, a2);
                a0 = fmaf(m[k].y, Wr[k][0].y, a0); a1 = fmaf(m[k].y, Wr[k][1].y, a1); a2 = fmaf(m[k].y, Wr[k][2].y, a2);
                a0 = fmaf(m[k].z, Wr[k][0].z, a0); a1 = fmaf(m[k].z, Wr[k][1].z, a1); a2 = fmaf(m[k].z, Wr[k][2].z, a2);
                a0 = fmaf(m[k].w, Wr[k][0].w, a0); a1 = fmaf(m[k].w, Wr[k][1].w, a1); a2 = fmaf(m[k].w, Wr[k][2].w, a2);
            }
            // span j = r partials; rows stride 36 words (conflict-free STS.32)
            redw[(3 * r + 0) * 36 + lane] = a0;
            redw[(3 * r + 1) * 36 + lane] = a1;
            redw[(3 * r + 2) * 36 + lane] = a2;
        }
        __syncwarp();

        // Transpose-reduce: lane < 30 sums its (j,t) row of 32 partials.
        // Row stride 36 words = 9 x 16B granules (odd) -> conflict-free LDS.128.
        if (lane < 30) {
            const float4* rp = (const float4*)(redw + lane * 36);
            float4 s0 = rp[0], s1 = rp[1], s2 = rp[2], s3 = rp[3];
            float4 s4 = rp[4], s5 = rp[5], s6 = rp[6], s7 = rp[7];
            s0 = make_float4(s0.x + s4.x, s0.y + s4.y, s0.z + s4.z, s0.w + s4.w);
            s1 = make_float4(s1.x + s5.x, s1.y + s5.y, s1.z + s5.z, s1.w + s5.w);
            s2 = make_float4(s2.x + s6.x, s2.y + s6.y, s2.z + s6.z, s2.w + s6.w);
            s3 = make_float4(s3.x + s7.x, s3.y + s7.y, s3.z + s7.z, s3.w + s7.w);
            s0 = make_float4(s0.x + s2.x, s0.y + s2.y, s0.z + s2.z, s0.w + s2.w);
            s1 = make_float4(s1.x + s3.x, s1.y + s3.y, s1.z + s3.z, s1.w + s3.w);
            const float tot = (s0.x + s1.x) + (s0.y + s1.y) + (s0.z + s1.z) + (s0.w + s1.w);

            const int j = lane / 3;
            const int t = lane - 3 * j;
            const int L = __ldg(lens + bn + j);
            out[(bn + j) * NUM_LABELS_ + c0 + t] =
                tot + g_len_logits[(L - 1) * NUM_LABELS_ + c0 + t];
        }
        __syncwarp();   // protect redw before next task overwrites it
    }
}

extern "C" void kernel_launch(void* const* d_in, const int* in_sizes, int n_in,
                              void* d_out, int out_size) {
    const float* we     = (const float*)d_in[0];   // word_embeddings [B,S,D]
    const int*   starts = (const int*)d_in[1];     // span_starts [B,N]
    const int*   lens   = (const int*)d_in[2];     // span_lens [B,N]
    const float* let    = (const float*)d_in[3];   // len_emb_table [MAX_LEN, LEN_EMB]
    const float* W      = (const float*)d_in[4];   // W [D+LEN_EMB, 9]
    const float* bvec   = (const float*)d_in[5];   // b [9]
    float* out = (float*)d_out;

    prep_kernel<<<(NUM_LABELS_ * D_ + 255) / 256, 256>>>(let, W, bvec);

    span_ner_kernel<<<GRID_, 96>>>(we, starts, lens, out);
}

// round 7
// speedup vs baseline: 1.2558x; 1.2558x over previous
#include <cuda_runtime.h>
#include <math_constants.h>

#define B_ 4
#define S_ 512
#define D_ 768
#define MAX_LEN_ 10
#define LEN_EMB_ 25
#define NUM_LABELS_ 9
#define N_ (S_ * MAX_LEN_)   // 5120

// len_logits[L-1][c] = len_emb_table[L-1] . W[768:, c] + b[c]
__device__ float g_len_logits[MAX_LEN_ * NUM_LABELS_];
// Transposed W head: Wt[c][d] = W[d][c]
__device__ __align__(16) float g_Wt[NUM_LABELS_][D_];

__global__ void prep_kernel(const float* __restrict__ len_emb_table,
                            const float* __restrict__ W,
                            const float* __restrict__ bvec) {
    int i = blockIdx.x * 256 + threadIdx.x;
    if (i < NUM_LABELS_ * D_) {
        int c = i / D_;
        int d = i % D_;
        g_Wt[c][d] = W[(size_t)d * NUM_LABELS_ + c];
    }
    if (blockIdx.x == 0 && threadIdx.x < MAX_LEN_ * NUM_LABELS_) {
        int L = threadIdx.x / NUM_LABELS_;
        int c = threadIdx.x % NUM_LABELS_;
        float s = bvec[c];
        #pragma unroll
        for (int k = 0; k < LEN_EMB_; k++) {
            s = fmaf(len_emb_table[L * LEN_EMB_ + k], W[(D_ + k) * NUM_LABELS_ + c], s);
        }
        g_len_logits[threadIdx.x] = s;
    }
}

__device__ __forceinline__ float4 max4(float4 a, float4 b) {
    float4 r;
    r.x = fmaxf(a.x, b.x); r.y = fmaxf(a.y, b.y);
    r.z = fmaxf(a.z, b.z); r.w = fmaxf(a.w, b.w);
    return r;
}

__device__ __forceinline__ unsigned long long pack2(float lo, float hi) {
    unsigned long long r;
    asm("mov.b64 %0, {%1, %2};" : "=l"(r) : "f"(lo), "f"(hi));
    return r;
}
__device__ __forceinline__ void fma2(unsigned long long& d,
                                     unsigned long long a, unsigned long long b) {
    asm("fma.rn.f32x2 %0, %1, %2, %0;" : "+l"(d) : "l"(a), "l"(b));
}
__device__ __forceinline__ float hsum2(unsigned long long v) {
    float lo, hi;
    asm("mov.b64 {%0, %1}, %2;" : "=f"(lo), "=f"(hi) : "l"(v));
    return lo + hi;
}

// One 96-thread block per (batch, start); warp w owns columns [3w, 3w+3).
// Fused streaming: each warp reads the 10 clamped rows (L1-shared across the
// 3 warps), keeps the running prefix-max of its 24 dims/lane, and emits the
// 3 packed-f32x2 dot partials for span j=r. Row loop FULLY unrolled so ptxas
// front-batches the LDGs (high MLP). One conflict-free transpose-reduce per
// task; zero shuffles, zero block barriers.
__global__ __launch_bounds__(96) void span_ner_kernel(
    const float* __restrict__ we,       // [B, S, D]
    const int*   __restrict__ starts,   // [B, N]
    const int*   __restrict__ lens,     // [B, N]
    float*       __restrict__ out)      // [B, N, 9]
{
    __shared__ float redw_s[3][30][36]; // per-warp scratch, 12.7 KB

    const int lane = threadIdx.x & 31;
    const int wid  = threadIdx.x >> 5;
    const int c0   = wid * 3;
    float* const redw = &redw_s[wid][0][0];

    // W slice, packed f32x2: lane owns dims 4*(lane+32k), k in [0,6).
    unsigned long long Wp[6][3][2];
    #pragma unroll
    for (int k = 0; k < 6; k++) {
        #pragma unroll
        for (int t = 0; t < 3; t++) {
            float4 w = *(const float4*)&g_Wt[c0 + t][4 * (lane + 32 * k)];
            Wp[k][t][0] = pack2(w.x, w.y);
            Wp[k][t][1] = pack2(w.z, w.w);
        }
    }

    const int bs = blockIdx.x;
    const int b = bs >> 9;               // /512
    const int s = bs & (S_ - 1);

    const size_t bn = (size_t)b * N_ + (size_t)s * MAX_LEN_;
    const int start = starts[bn];
    const int smax1 = S_ - start - 1;    // >= 0
    const float* base = we + ((size_t)b * S_ + start) * D_;

    float4 m[6];
    #pragma unroll
    for (int k = 0; k < 6; k++)
        m[k] = make_float4(-CUDART_INF_F, -CUDART_INF_F, -CUDART_INF_F, -CUDART_INF_F);

    // pooled(j) = prefix max through clamped row j (clamped dups idempotent).
    #pragma unroll
    for (int r = 0; r < MAX_LEN_; r++) {
        const int rc = (r < smax1) ? r : smax1;
        const float* rowp = base + (size_t)rc * D_;
        float4 v[6];
        #pragma unroll
        for (int k = 0; k < 6; k++)
            v[k] = __ldg((const float4*)(rowp + 4 * (lane + 32 * k)));
        #pragma unroll
        for (int k = 0; k < 6; k++)
            m[k] = max4(m[k], v[k]);

        unsigned long long A0 = 0ull, A1 = 0ull, A2 = 0ull;
        #pragma unroll
        for (int k = 0; k < 6; k++) {
            const unsigned long long p0 = pack2(m[k].x, m[k].y);
            const unsigned long long p1 = pack2(m[k].z, m[k].w);
            fma2(A0, p0, Wp[k][0][0]); fma2(A0, p1, Wp[k][0][1]);
            fma2(A1, p0, Wp[k][1][0]); fma2(A1, p1, Wp[k][1][1]);
            fma2(A2, p0, Wp[k][2][0]); fma2(A2, p1, Wp[k][2][1]);
        }
        // span j = r partials; rows stride 36 words (conflict-free STS.32)
        redw[(3 * r + 0) * 36 + lane] = hsum2(A0);
        redw[(3 * r + 1) * 36 + lane] = hsum2(A1);
        redw[(3 * r + 2) * 36 + lane] = hsum2(A2);
    }
    __syncwarp();

    // Transpose-reduce: lane < 30 sums its (j,t) row of 32 partials.
    // Row stride 36 words = 9 x 16B granules (odd) -> conflict-free LDS.128.
    if (lane < 30) {
        const float4* rp = (const float4*)(redw + lane * 36);
        float4 s0 = rp[0], s1 = rp[1], s2 = rp[2], s3 = rp[3];
        float4 s4 = rp[4], s5 = rp[5], s6 = rp[6], s7 = rp[7];
        s0 = make_float4(s0.x + s4.x, s0.y + s4.y, s0.z + s4.z, s0.w + s4.w);
        s1 = make_float4(s1.x + s5.x, s1.y + s5.y, s1.z + s5.z, s1.w + s5.w);
        s2 = make_float4(s2.x + s6.x, s2.y + s6.y, s2.z + s6.z, s2.w + s6.w);
        s3 = make_float4(s3.x + s7.x, s3.y + s7.y, s3.z + s7.z, s3.w + s7.w);
        s0 = make_float4(s0.x + s2.x, s0.y + s2.y, s0.z + s2.z, s0.w + s2.w);
        s1 = make_float4(s1.x + s3.x, s1.y + s3.y, s1.z + s3.z, s1.w + s3.w);
        const float tot = (s0.x + s1.x) + (s0.y + s1.y) + (s0.z + s1.z) + (s0.w + s1.w);

        const int j = lane / 3;
        const int t = lane - 3 * j;
        const int L = __ldg(lens + bn + j);
        out[(bn + j) * NUM_LABELS_ + c0 + t] =
            tot + g_len_logits[(L - 1) * NUM_LABELS_ + c0 + t];
    }
}

extern "C" void kernel_launch(void* const* d_in, const int* in_sizes, int n_in,
                              void* d_out, int out_size) {
    const float* we     = (const float*)d_in[0];   // word_embeddings [B,S,D]
    const int*   starts = (const int*)d_in[1];     // span_starts [B,N]
    const int*   lens   = (const int*)d_in[2];     // span_lens [B,N]
    const float* let    = (const float*)d_in[3];   // len_emb_table [MAX_LEN, LEN_EMB]
    const float* W      = (const float*)d_in[4];   // W [D+LEN_EMB, 9]
    const float* bvec   = (const float*)d_in[5];   // b [9]
    float* out = (float*)d_out;

    prep_kernel<<<(NUM_LABELS_ * D_ + 255) / 256, 256>>>(let, W, bvec);

    span_ner_kernel<<<B_ * S_, 96>>>(we, starts, lens, out);
}